// round 2
// baseline (speedup 1.0000x reference)
#include <cuda_runtime.h>
#include <cuda_bf16.h>
#include <cstdint>

#define NMAX 100000
#define EMAX 3200000
#define HC   32
#define GMAX 512
#define FULL 0xffffffffu

// ---------------- device scratch ----------------
__device__ float g_h  [(size_t)NMAX * HC];
__device__ float g_x  [(size_t)NMAX * HC];
__device__ float g_als[(size_t)NMAX * 4];
__device__ float g_ald[(size_t)NMAX * 4];
__device__ int   g_deg[NMAX];
__device__ int   g_cur[NMAX];
__device__ int   g_off[NMAX + 1];
__device__ int   g_csr[EMAX];
__device__ float g_gsum[GMAX * HC];
__device__ float g_gcnt[GMAX];
__device__ int   g_flags[2];
__device__ int   g_part[256];

// ---------------- dtype detection ----------------
__global__ void k_detect(const int* __restrict__ ei, int ei_elems,
                         const int* __restrict__ batch, int n)
{
    if (blockIdx.x != 0 || threadIdx.x != 0) return;
    int all0 = 1;
    {
        long long cnt = ei_elems;
        long long step = (cnt - 2) / 128; if (step < 1) step = 1;
        for (int k = 0; k < 64; k++) {
            long long idx = 1 + 2 * step * k;
            if (idx >= cnt) idx = cnt - 1;
            if (!(idx & 1)) idx -= 1;
            if (ei[idx] != 0) { all0 = 0; break; }
        }
    }
    g_flags[0] = all0;
    all0 = 1;
    {
        long long lo = 2001, hi = n - 2;
        long long step = (hi - lo) / 64; if (step < 1) step = 1;
        for (int k = 0; k < 64; k++) {
            long long idx = lo + step * k;
            idx |= 1;
            if (idx >= n) idx = (n - 2) | 1;
            if (batch[idx] != 0) { all0 = 0; break; }
        }
    }
    g_flags[1] = all0;
}

// ---------------- init ----------------
__global__ void k_init(int n, int g)
{
    int i = blockIdx.x * blockDim.x + threadIdx.x;
    if (i < n) { g_deg[i] = 0; g_cur[i] = 0; }
    if (i < g * HC) g_gsum[i] = 0.f;
    if (i < g)      g_gcnt[i] = 0.f;
}

// ---------------- degree histogram ----------------
__global__ void k_hist(const void* __restrict__ ei, int E)
{
    int e = blockIdx.x * blockDim.x + threadIdx.x;
    if (e >= E) return;
    int d;
    if (g_flags[0]) d = (int)((const long long*)ei)[(long long)E + e];
    else            d = ((const int*)ei)[E + e];
    atomicAdd(&g_deg[d], 1);
}

// ---------------- exclusive scan ----------------
__global__ void k_scan1(int n)
{
    __shared__ int sh[1024];
    int i = blockIdx.x * 1024 + threadIdx.x;
    int v = (i < n) ? g_deg[i] : 0;
    sh[threadIdx.x] = v;
    __syncthreads();
    for (int d = 1; d < 1024; d <<= 1) {
        int t = 0;
        if ((int)threadIdx.x >= d) t = sh[threadIdx.x - d];
        __syncthreads();
        sh[threadIdx.x] += t;
        __syncthreads();
    }
    if (i < n) g_off[i] = sh[threadIdx.x] - v;
    if (threadIdx.x == 1023) g_part[blockIdx.x] = sh[1023];
}

__global__ void k_scan2(int nblocks, int n)
{
    __shared__ int sh[256];
    if (threadIdx.x < nblocks) sh[threadIdx.x] = g_part[threadIdx.x];
    __syncthreads();
    if (threadIdx.x == 0) {
        int run = 0;
        for (int b = 0; b < nblocks; b++) { int t = sh[b]; sh[b] = run; run += t; }
        g_off[n] = run;
    }
    __syncthreads();
    if (threadIdx.x < nblocks) g_part[threadIdx.x] = sh[threadIdx.x];
}

__global__ void k_scan3(int n)
{
    int i = blockIdx.x * 1024 + threadIdx.x;
    if (i < n) g_off[i] += g_part[blockIdx.x];
}

// ---------------- scatter edges into CSR ----------------
__global__ void k_scatter(const void* __restrict__ ei, int E)
{
    int e = blockIdx.x * blockDim.x + threadIdx.x;
    if (e >= E) return;
    int s, d;
    if (g_flags[0]) {
        const long long* p = (const long long*)ei;
        s = (int)p[e]; d = (int)p[(long long)E + e];
    } else {
        const int* p = (const int*)ei;
        s = p[e]; d = p[E + e];
    }
    int pos = g_off[d] + atomicAdd(&g_cur[d], 1);
    g_csr[pos] = s;
}

// ---------------- GEMM + attention-logit precompute ----------------
template<int DIN>
__global__ void k_gemm(const float* __restrict__ xp, const float* __restrict__ W,
                       const float* __restrict__ asv, const float* __restrict__ adv, int n)
{
    __shared__ float Ws[DIN * 32];
    __shared__ float Ss[32], Sd[32];
    for (int i = threadIdx.x; i < DIN * 32; i += blockDim.x) Ws[i] = W[i];
    if (threadIdx.x < 32) { Ss[threadIdx.x] = asv[threadIdx.x]; Sd[threadIdx.x] = adv[threadIdx.x]; }
    __syncthreads();

    int node = blockIdx.x * blockDim.x + threadIdx.x;
    if (node >= n) return;

    const float* xin = xp ? xp : g_x;
    float acc[32];
#pragma unroll
    for (int j = 0; j < 32; j++) acc[j] = 0.f;

    const float4* xr = (const float4*)(xin + (size_t)node * DIN);
#pragma unroll 4
    for (int k4 = 0; k4 < DIN / 4; k4++) {
        float4 xv = __ldg(&xr[k4]);
        float xk[4] = { xv.x, xv.y, xv.z, xv.w };
#pragma unroll
        for (int kk = 0; kk < 4; kk++) {
            const float4* wr = (const float4*)&Ws[(k4 * 4 + kk) * 32];
#pragma unroll
            for (int j4 = 0; j4 < 8; j4++) {
                float4 w = wr[j4];
                acc[j4 * 4 + 0] += xk[kk] * w.x;
                acc[j4 * 4 + 1] += xk[kk] * w.y;
                acc[j4 * 4 + 2] += xk[kk] * w.z;
                acc[j4 * 4 + 3] += xk[kk] * w.w;
            }
        }
    }

    float alS[4], alD[4];
#pragma unroll
    for (int hh = 0; hh < 4; hh++) {
        float a = 0.f, b = 0.f;
#pragma unroll
        for (int c = 0; c < 8; c++) {
            a += acc[hh * 8 + c] * Ss[hh * 8 + c];
            b += acc[hh * 8 + c] * Sd[hh * 8 + c];
        }
        alS[hh] = a; alD[hh] = b;
    }

    float4* hrow = (float4*)(g_h + (size_t)node * HC);
#pragma unroll
    for (int q = 0; q < 8; q++)
        hrow[q] = make_float4(acc[q*4], acc[q*4+1], acc[q*4+2], acc[q*4+3]);
    *(float4*)(g_als + (size_t)node * 4) = make_float4(alS[0], alS[1], alS[2], alS[3]);
    *(float4*)(g_ald + (size_t)node * 4) = make_float4(alD[0], alD[1], alD[2], alD[3]);
}

// ---------------- warp-per-node aggregation ----------------
// lane = hh*8 + cc : output channel. Edges processed in batches of 32.
// Edge-parallel phase: lane covers edges base+(lane&7)+8k, k=0..3, for its OWN head.
// Self-loop handled implicitly in the prologue.
__global__ void __launch_bounds__(256) k_agg(const float* __restrict__ bias, int n)
{
    int node = (blockIdx.x * blockDim.x + threadIdx.x) >> 5;
    int lane = threadIdx.x & 31;
    if (node >= n) return;
    int hh  = lane >> 3;
    int oct = lane & 7;

    int off = g_off[node];
    int deg = g_off[node + 1] - off;

    float ad = __ldg(&g_ald[(size_t)node * 4 + hh]);

    // self-loop prologue: w_self = 1 with m = e_self
    float es = __ldg(&g_als[(size_t)node * 4 + hh]) + ad;
    es = fmaxf(es, 0.2f * es);
    float m = es;
    float s = 1.f;
    float acc = __ldg(&g_h[(size_t)node * HC + lane]);

    for (int base = 0; base < deg; base += 32) {
        int cnt = min(32, deg - base);
        int eb = off + base + oct;
        int s0 = 0, s1 = 0, s2 = 0, s3 = 0;
        float e0 = -1e30f, e1 = -1e30f, e2 = -1e30f, e3 = -1e30f;
        if (oct < cnt)      { s0 = __ldg(&g_csr[eb]);      float a = __ldg(&g_als[(size_t)s0*4+hh]) + ad; e0 = fmaxf(a, 0.2f*a); }
        if (oct + 8 < cnt)  { s1 = __ldg(&g_csr[eb + 8]);  float a = __ldg(&g_als[(size_t)s1*4+hh]) + ad; e1 = fmaxf(a, 0.2f*a); }
        if (oct + 16 < cnt) { s2 = __ldg(&g_csr[eb + 16]); float a = __ldg(&g_als[(size_t)s2*4+hh]) + ad; e2 = fmaxf(a, 0.2f*a); }
        if (oct + 24 < cnt) { s3 = __ldg(&g_csr[eb + 24]); float a = __ldg(&g_als[(size_t)s3*4+hh]) + ad; e3 = fmaxf(a, 0.2f*a); }

        // batch max per head (octet reduction)
        float bm = fmaxf(fmaxf(e0, e1), fmaxf(e2, e3));
        bm = fmaxf(bm, __shfl_xor_sync(FULL, bm, 1));
        bm = fmaxf(bm, __shfl_xor_sync(FULL, bm, 2));
        bm = fmaxf(bm, __shfl_xor_sync(FULL, bm, 4));

        float mn = fmaxf(m, bm);
        float c  = __expf(m - mn);
        s *= c; acc *= c; m = mn;

        float w0 = __expf(e0 - mn);
        float w1 = __expf(e1 - mn);
        float w2 = __expf(e2 - mn);
        float w3 = __expf(e3 - mn);

        float sw = (w0 + w1) + (w2 + w3);
        sw += __shfl_xor_sync(FULL, sw, 1);
        sw += __shfl_xor_sync(FULL, sw, 2);
        sw += __shfl_xor_sync(FULL, sw, 4);
        s += sw;

        int hb = hh << 3;
        if (cnt == 32) {
#pragma unroll
            for (int j = 0; j < 32; j++) {
                int k = j >> 3, so = j & 7;
                int sj; float wj;
                if      (k == 0) { sj = __shfl_sync(FULL, s0, so); wj = __shfl_sync(FULL, w0, hb | so); }
                else if (k == 1) { sj = __shfl_sync(FULL, s1, so); wj = __shfl_sync(FULL, w1, hb | so); }
                else if (k == 2) { sj = __shfl_sync(FULL, s2, so); wj = __shfl_sync(FULL, w2, hb | so); }
                else             { sj = __shfl_sync(FULL, s3, so); wj = __shfl_sync(FULL, w3, hb | so); }
                float hv = __ldg(&g_h[(size_t)sj * HC + lane]);
                acc += wj * hv;
            }
        } else {
            for (int j = 0; j < cnt; j++) {
                int k = j >> 3, so = j & 7;
                int sj; float wj;
                if      (k == 0) { sj = __shfl_sync(FULL, s0, so); wj = __shfl_sync(FULL, w0, hb | so); }
                else if (k == 1) { sj = __shfl_sync(FULL, s1, so); wj = __shfl_sync(FULL, w1, hb | so); }
                else if (k == 2) { sj = __shfl_sync(FULL, s2, so); wj = __shfl_sync(FULL, w2, hb | so); }
                else             { sj = __shfl_sync(FULL, s3, so); wj = __shfl_sync(FULL, w3, hb | so); }
                float hv = __ldg(&g_h[(size_t)sj * HC + lane]);
                acc += wj * hv;
            }
        }
    }

    float v = acc / s + __ldg(&bias[lane]);
    v = v > 0.f ? v : expm1f(v);
    g_x[(size_t)node * HC + lane] = v;
}

// ---------------- global mean pool: warp-segmented ----------------
__global__ void k_pool(const void* __restrict__ batch, int n)
{
    int warp = (blockIdx.x * blockDim.x + threadIdx.x) >> 5;
    int lane = threadIdx.x & 31;
    int base = warp * 32;
    if (base >= n) return;
    int is64 = g_flags[1];

    float accv = 0.f; int cnt = 0; int curg = -1;
    for (int j = 0; j < 32; j++) {
        int node = base + j;
        if (node >= n) break;
        int gg;
        if (is64) gg = (int)((const long long*)batch)[node];
        else      gg = ((const int*)batch)[node];
        if (gg != curg) {
            if (curg >= 0) {
                atomicAdd(&g_gsum[curg * HC + lane], accv);
                if (lane == 0) atomicAdd(&g_gcnt[curg], (float)cnt);
            }
            accv = 0.f; cnt = 0; curg = gg;
        }
        accv += g_x[(size_t)node * HC + lane];
        cnt++;
    }
    if (curg >= 0) {
        atomicAdd(&g_gsum[curg * HC + lane], accv);
        if (lane == 0) atomicAdd(&g_gcnt[curg], (float)cnt);
    }
}

// ---------------- final FC ----------------
__global__ void k_final(const float* __restrict__ fcw, const float* __restrict__ fcb,
                        float* __restrict__ out, int gcount)
{
    int g = blockIdx.x * blockDim.x + threadIdx.x;
    if (g >= gcount) return;
    float cnt = fmaxf(g_gcnt[g], 1.f);
    float acc = fcb[0];
    const float* s = g_gsum + g * HC;
#pragma unroll
    for (int c = 0; c < HC; c++) acc += (s[c] / cnt) * fcw[c];
    out[g] = acc;
}

// ---------------- host ----------------
extern "C" void kernel_launch(void* const* d_in, const int* in_sizes, int n_in,
                              void* d_out, int out_size)
{
    const float* x     = (const float*)d_in[0];
    const void*  ei    = d_in[1];
    const void*  batch = d_in[2];
    const float* W1 = (const float*)d_in[3];
    const float* as1= (const float*)d_in[4];
    const float* ad1= (const float*)d_in[5];
    const float* b1 = (const float*)d_in[6];
    const float* W2 = (const float*)d_in[7];
    const float* as2= (const float*)d_in[8];
    const float* ad2= (const float*)d_in[9];
    const float* b2 = (const float*)d_in[10];
    const float* W3 = (const float*)d_in[11];
    const float* as3= (const float*)d_in[12];
    const float* ad3= (const float*)d_in[13];
    const float* b3 = (const float*)d_in[14];
    const float* W4 = (const float*)d_in[15];
    const float* as4= (const float*)d_in[16];
    const float* ad4= (const float*)d_in[17];
    const float* b4 = (const float*)d_in[18];
    const float* fcw= (const float*)d_in[19];
    const float* fcb= (const float*)d_in[20];

    int nN = in_sizes[2];
    int E  = in_sizes[1] / 2;
    int G  = out_size;
    float* out = (float*)d_out;

    k_detect<<<1, 32>>>((const int*)ei, in_sizes[1], (const int*)batch, nN);

    {
        int mx = nN;
        if (G * HC > mx) mx = G * HC;
        k_init<<<(mx + 255) / 256, 256>>>(nN, G);
    }

    k_hist<<<(E + 255) / 256, 256>>>(ei, E);

    int nb = (nN + 1023) / 1024;
    k_scan1<<<nb, 1024>>>(nN);
    k_scan2<<<1, 256>>>(nb, nN);
    k_scan3<<<nb, 1024>>>(nN);

    k_scatter<<<(E + 255) / 256, 256>>>(ei, E);

    int gb = (nN + 255) / 256;
    int ab = (nN * 32 + 255) / 256;   // warp per node

    k_gemm<128><<<gb, 256>>>(x,      W1, as1, ad1, nN);
    k_agg<<<ab, 256>>>(b1, nN);
    k_gemm<32><<<gb, 256>>>(nullptr, W2, as2, ad2, nN);
    k_agg<<<ab, 256>>>(b2, nN);
    k_gemm<32><<<gb, 256>>>(nullptr, W3, as3, ad3, nN);
    k_agg<<<ab, 256>>>(b3, nN);
    k_gemm<32><<<gb, 256>>>(nullptr, W4, as4, ad4, nN);
    k_agg<<<ab, 256>>>(b4, nN);

    k_pool<<<(nN + 255) / 256, 256>>>(batch, nN);
    k_final<<<(G + 255) / 256, 256>>>(fcw, fcb, out, G);
}

// round 3
// speedup vs baseline: 1.7121x; 1.7121x over previous
#include <cuda_runtime.h>
#include <cuda_bf16.h>
#include <cstdint>

#define NMAX 100000
#define EMAX 3200000
#define HC   32
#define GMAX 512
#define FULL 0xffffffffu

// ---------------- device scratch ----------------
__device__ float g_h  [(size_t)NMAX * HC];
__device__ float g_x  [(size_t)NMAX * HC];
__device__ float g_als[(size_t)NMAX * 4];
__device__ float g_ald[(size_t)NMAX * 4];
__device__ int   g_deg[NMAX];
__device__ int   g_cur[NMAX];
__device__ int   g_off[NMAX + 1];
__device__ int   g_csr[EMAX];
__device__ float g_gsum[GMAX * HC];
__device__ float g_gcnt[GMAX];
__device__ int   g_flags[2];
__device__ int   g_part[256];

// ---------------- dtype detection ----------------
__global__ void k_detect(const int* __restrict__ ei, int ei_elems,
                         const int* __restrict__ batch, int n)
{
    if (blockIdx.x != 0 || threadIdx.x != 0) return;
    int all0 = 1;
    {
        long long cnt = ei_elems;
        long long step = (cnt - 2) / 128; if (step < 1) step = 1;
        for (int k = 0; k < 64; k++) {
            long long idx = 1 + 2 * step * k;
            if (idx >= cnt) idx = cnt - 1;
            if (!(idx & 1)) idx -= 1;
            if (ei[idx] != 0) { all0 = 0; break; }
        }
    }
    g_flags[0] = all0;
    all0 = 1;
    {
        long long lo = 2001, hi = n - 2;
        long long step = (hi - lo) / 64; if (step < 1) step = 1;
        for (int k = 0; k < 64; k++) {
            long long idx = lo + step * k;
            idx |= 1;
            if (idx >= n) idx = (n - 2) | 1;
            if (batch[idx] != 0) { all0 = 0; break; }
        }
    }
    g_flags[1] = all0;
}

// ---------------- init ----------------
__global__ void k_init(int n, int g)
{
    int i = blockIdx.x * blockDim.x + threadIdx.x;
    if (i < n) { g_deg[i] = 0; g_cur[i] = 0; }
    if (i < g * HC) g_gsum[i] = 0.f;
    if (i < g)      g_gcnt[i] = 0.f;
}

// ---------------- degree histogram ----------------
__global__ void k_hist(const void* __restrict__ ei, int E)
{
    int e = blockIdx.x * blockDim.x + threadIdx.x;
    if (e >= E) return;
    int d;
    if (g_flags[0]) d = (int)((const long long*)ei)[(long long)E + e];
    else            d = ((const int*)ei)[E + e];
    atomicAdd(&g_deg[d], 1);
}

// ---------------- exclusive scan ----------------
__global__ void k_scan1(int n)
{
    __shared__ int sh[1024];
    int i = blockIdx.x * 1024 + threadIdx.x;
    int v = (i < n) ? g_deg[i] : 0;
    sh[threadIdx.x] = v;
    __syncthreads();
    for (int d = 1; d < 1024; d <<= 1) {
        int t = 0;
        if ((int)threadIdx.x >= d) t = sh[threadIdx.x - d];
        __syncthreads();
        sh[threadIdx.x] += t;
        __syncthreads();
    }
    if (i < n) g_off[i] = sh[threadIdx.x] - v;
    if (threadIdx.x == 1023) g_part[blockIdx.x] = sh[1023];
}

__global__ void k_scan2(int nblocks, int n)
{
    __shared__ int sh[256];
    if (threadIdx.x < nblocks) sh[threadIdx.x] = g_part[threadIdx.x];
    __syncthreads();
    if (threadIdx.x == 0) {
        int run = 0;
        for (int b = 0; b < nblocks; b++) { int t = sh[b]; sh[b] = run; run += t; }
        g_off[n] = run;
    }
    __syncthreads();
    if (threadIdx.x < nblocks) g_part[threadIdx.x] = sh[threadIdx.x];
}

__global__ void k_scan3(int n)
{
    int i = blockIdx.x * 1024 + threadIdx.x;
    if (i < n) g_off[i] += g_part[blockIdx.x];
}

// ---------------- scatter edges into CSR ----------------
__global__ void k_scatter(const void* __restrict__ ei, int E)
{
    int e = blockIdx.x * blockDim.x + threadIdx.x;
    if (e >= E) return;
    int s, d;
    if (g_flags[0]) {
        const long long* p = (const long long*)ei;
        s = (int)p[e]; d = (int)p[(long long)E + e];
    } else {
        const int* p = (const int*)ei;
        s = p[e]; d = p[E + e];
    }
    int pos = g_off[d] + atomicAdd(&g_cur[d], 1);
    g_csr[pos] = s;
}

// ---------------- GEMM + attention-logit precompute ----------------
template<int DIN>
__global__ void k_gemm(const float* __restrict__ xp, const float* __restrict__ W,
                       const float* __restrict__ asv, const float* __restrict__ adv, int n)
{
    __shared__ float Ws[DIN * 32];
    __shared__ float Ss[32], Sd[32];
    for (int i = threadIdx.x; i < DIN * 32; i += blockDim.x) Ws[i] = W[i];
    if (threadIdx.x < 32) { Ss[threadIdx.x] = asv[threadIdx.x]; Sd[threadIdx.x] = adv[threadIdx.x]; }
    __syncthreads();

    int node = blockIdx.x * blockDim.x + threadIdx.x;
    if (node >= n) return;

    const float* xin = xp ? xp : g_x;
    float acc[32];
#pragma unroll
    for (int j = 0; j < 32; j++) acc[j] = 0.f;

    const float4* xr = (const float4*)(xin + (size_t)node * DIN);
#pragma unroll 4
    for (int k4 = 0; k4 < DIN / 4; k4++) {
        float4 xv = __ldg(&xr[k4]);
        float xk[4] = { xv.x, xv.y, xv.z, xv.w };
#pragma unroll
        for (int kk = 0; kk < 4; kk++) {
            const float4* wr = (const float4*)&Ws[(k4 * 4 + kk) * 32];
#pragma unroll
            for (int j4 = 0; j4 < 8; j4++) {
                float4 w = wr[j4];
                acc[j4 * 4 + 0] += xk[kk] * w.x;
                acc[j4 * 4 + 1] += xk[kk] * w.y;
                acc[j4 * 4 + 2] += xk[kk] * w.z;
                acc[j4 * 4 + 3] += xk[kk] * w.w;
            }
        }
    }

    float alS[4], alD[4];
#pragma unroll
    for (int hh = 0; hh < 4; hh++) {
        float a = 0.f, b = 0.f;
#pragma unroll
        for (int c = 0; c < 8; c++) {
            a += acc[hh * 8 + c] * Ss[hh * 8 + c];
            b += acc[hh * 8 + c] * Sd[hh * 8 + c];
        }
        alS[hh] = a; alD[hh] = b;
    }

    float4* hrow = (float4*)(g_h + (size_t)node * HC);
#pragma unroll
    for (int q = 0; q < 8; q++)
        hrow[q] = make_float4(acc[q*4], acc[q*4+1], acc[q*4+2], acc[q*4+3]);
    *(float4*)(g_als + (size_t)node * 4) = make_float4(alS[0], alS[1], alS[2], alS[3]);
    *(float4*)(g_ald + (size_t)node * 4) = make_float4(alD[0], alD[1], alD[2], alD[3]);
}

// ---------------- aggregation: 4 lanes per node, fixed-shift softmax ----------------
// softmax is shift-invariant: use the self-loop logit es as the shift.
// No max pass, no online rescale -> per-edge work has no serial recurrence
// except 9 independent FFMA accumulation chains (lat 4).
__global__ void __launch_bounds__(256) k_agg(const float* __restrict__ bias, int n)
{
    int idx = blockIdx.x * blockDim.x + threadIdx.x;
    int node = idx >> 2;
    int hh   = idx & 3;
    if (node >= n) return;

    int off = g_off[node];
    int end = g_off[node + 1];
    float ad = __ldg(&g_ald[(size_t)node * 4 + hh]);

    // self-loop: w = exp(es - es) = 1
    float es = __ldg(&g_als[(size_t)node * 4 + hh]) + ad;
    es = fmaxf(es, 0.2f * es);

    float s = 1.f;
    const float4* hs = (const float4*)(g_h + (size_t)node * HC + hh * 8);
    float4 h0 = __ldg(hs);
    float4 h1 = __ldg(hs + 1);
    float a0 = h0.x, a1 = h0.y, a2 = h0.z, a3 = h0.w;
    float a4 = h1.x, a5 = h1.y, a6 = h1.z, a7 = h1.w;

#pragma unroll 4
    for (int i = off; i < end; i++) {
        int sidx = __ldg(&g_csr[i]);
        float e = __ldg(&g_als[(size_t)sidx * 4 + hh]) + ad;
        e = fmaxf(e, 0.2f * e);                 // leaky_relu(0.2)
        float w = __expf(e - es);
        const float4* hp = (const float4*)(g_h + (size_t)sidx * HC + hh * 8);
        float4 v0 = __ldg(hp);
        float4 v1 = __ldg(hp + 1);
        s  += w;
        a0 += w * v0.x;  a1 += w * v0.y;  a2 += w * v0.z;  a3 += w * v0.w;
        a4 += w * v1.x;  a5 += w * v1.y;  a6 += w * v1.z;  a7 += w * v1.w;
    }

    float inv = 1.f / s;
    const float* bp = bias + hh * 8;
    float v[8] = { a0*inv, a1*inv, a2*inv, a3*inv, a4*inv, a5*inv, a6*inv, a7*inv };
#pragma unroll
    for (int c = 0; c < 8; c++) {
        float t = v[c] + bp[c];
        v[c] = t > 0.f ? t : expm1f(t);         // elu
    }
    float4* xo = (float4*)(g_x + (size_t)node * HC + hh * 8);
    xo[0] = make_float4(v[0], v[1], v[2], v[3]);
    xo[1] = make_float4(v[4], v[5], v[6], v[7]);
}

// ---------------- global mean pool: warp-segmented ----------------
__global__ void k_pool(const void* __restrict__ batch, int n)
{
    int warp = (blockIdx.x * blockDim.x + threadIdx.x) >> 5;
    int lane = threadIdx.x & 31;
    int base = warp * 32;
    if (base >= n) return;
    int is64 = g_flags[1];

    float accv = 0.f; int cnt = 0; int curg = -1;
    for (int j = 0; j < 32; j++) {
        int node = base + j;
        if (node >= n) break;
        int gg;
        if (is64) gg = (int)((const long long*)batch)[node];
        else      gg = ((const int*)batch)[node];
        if (gg != curg) {
            if (curg >= 0) {
                atomicAdd(&g_gsum[curg * HC + lane], accv);
                if (lane == 0) atomicAdd(&g_gcnt[curg], (float)cnt);
            }
            accv = 0.f; cnt = 0; curg = gg;
        }
        accv += g_x[(size_t)node * HC + lane];
        cnt++;
    }
    if (curg >= 0) {
        atomicAdd(&g_gsum[curg * HC + lane], accv);
        if (lane == 0) atomicAdd(&g_gcnt[curg], (float)cnt);
    }
}

// ---------------- final FC ----------------
__global__ void k_final(const float* __restrict__ fcw, const float* __restrict__ fcb,
                        float* __restrict__ out, int gcount)
{
    int g = blockIdx.x * blockDim.x + threadIdx.x;
    if (g >= gcount) return;
    float cnt = fmaxf(g_gcnt[g], 1.f);
    float acc = fcb[0];
    const float* s = g_gsum + g * HC;
#pragma unroll
    for (int c = 0; c < HC; c++) acc += (s[c] / cnt) * fcw[c];
    out[g] = acc;
}

// ---------------- host ----------------
extern "C" void kernel_launch(void* const* d_in, const int* in_sizes, int n_in,
                              void* d_out, int out_size)
{
    const float* x     = (const float*)d_in[0];
    const void*  ei    = d_in[1];
    const void*  batch = d_in[2];
    const float* W1 = (const float*)d_in[3];
    const float* as1= (const float*)d_in[4];
    const float* ad1= (const float*)d_in[5];
    const float* b1 = (const float*)d_in[6];
    const float* W2 = (const float*)d_in[7];
    const float* as2= (const float*)d_in[8];
    const float* ad2= (const float*)d_in[9];
    const float* b2 = (const float*)d_in[10];
    const float* W3 = (const float*)d_in[11];
    const float* as3= (const float*)d_in[12];
    const float* ad3= (const float*)d_in[13];
    const float* b3 = (const float*)d_in[14];
    const float* W4 = (const float*)d_in[15];
    const float* as4= (const float*)d_in[16];
    const float* ad4= (const float*)d_in[17];
    const float* b4 = (const float*)d_in[18];
    const float* fcw= (const float*)d_in[19];
    const float* fcb= (const float*)d_in[20];

    int nN = in_sizes[2];
    int E  = in_sizes[1] / 2;
    int G  = out_size;
    float* out = (float*)d_out;

    k_detect<<<1, 32>>>((const int*)ei, in_sizes[1], (const int*)batch, nN);

    {
        int mx = nN;
        if (G * HC > mx) mx = G * HC;
        k_init<<<(mx + 255) / 256, 256>>>(nN, G);
    }

    k_hist<<<(E + 255) / 256, 256>>>(ei, E);

    int nb = (nN + 1023) / 1024;
    k_scan1<<<nb, 1024>>>(nN);
    k_scan2<<<1, 256>>>(nb, nN);
    k_scan3<<<nb, 1024>>>(nN);

    k_scatter<<<(E + 255) / 256, 256>>>(ei, E);

    int gb = (nN + 255) / 256;
    int ab = (nN * 4 + 255) / 256;    // 4 lanes per node

    k_gemm<128><<<gb, 256>>>(x,      W1, as1, ad1, nN);
    k_agg<<<ab, 256>>>(b1, nN);
    k_gemm<32><<<gb, 256>>>(nullptr, W2, as2, ad2, nN);
    k_agg<<<ab, 256>>>(b2, nN);
    k_gemm<32><<<gb, 256>>>(nullptr, W3, as3, ad3, nN);
    k_agg<<<ab, 256>>>(b3, nN);
    k_gemm<32><<<gb, 256>>>(nullptr, W4, as4, ad4, nN);
    k_agg<<<ab, 256>>>(b4, nN);

    k_pool<<<(nN + 255) / 256, 256>>>(batch, nN);
    k_final<<<(G + 255) / 256, 256>>>(fcw, fcb, out, G);
}

// round 4
// speedup vs baseline: 1.8975x; 1.1083x over previous
#include <cuda_runtime.h>
#include <cuda_fp16.h>
#include <cstdint>

#define NMAX 100000
#define EMAX 3200000
#define HC   32
#define GMAX 512
#define FULL 0xffffffffu

// ---------------- device scratch ----------------
__device__ __align__(16) __half2 g_h16[(size_t)NMAX * 16];   // h in fp16: 16 half2 / node
__device__ float g_x  [(size_t)NMAX * HC];
__device__ float g_als[(size_t)NMAX * 4];
__device__ float g_ald[(size_t)NMAX * 4];
__device__ int   g_deg[NMAX];
__device__ int   g_cur[NMAX];
__device__ int   g_off[NMAX + 1];
__device__ int   g_csr[EMAX];
__device__ float g_gsum[GMAX * HC];
__device__ float g_gcnt[GMAX];
__device__ int   g_flags[2];
__device__ int   g_part[256];

// ---------------- dtype detection ----------------
__global__ void k_detect(const int* __restrict__ ei, int ei_elems,
                         const int* __restrict__ batch, int n)
{
    if (blockIdx.x != 0 || threadIdx.x != 0) return;
    int all0 = 1;
    {
        long long cnt = ei_elems;
        long long step = (cnt - 2) / 128; if (step < 1) step = 1;
        for (int k = 0; k < 64; k++) {
            long long idx = 1 + 2 * step * k;
            if (idx >= cnt) idx = cnt - 1;
            if (!(idx & 1)) idx -= 1;
            if (ei[idx] != 0) { all0 = 0; break; }
        }
    }
    g_flags[0] = all0;
    all0 = 1;
    {
        long long lo = 2001, hi = n - 2;
        long long step = (hi - lo) / 64; if (step < 1) step = 1;
        for (int k = 0; k < 64; k++) {
            long long idx = lo + step * k;
            idx |= 1;
            if (idx >= n) idx = (n - 2) | 1;
            if (batch[idx] != 0) { all0 = 0; break; }
        }
    }
    g_flags[1] = all0;
}

// ---------------- init ----------------
__global__ void k_init(int n, int g)
{
    int i = blockIdx.x * blockDim.x + threadIdx.x;
    if (i < n) { g_deg[i] = 0; g_cur[i] = 0; }
    if (i < g * HC) g_gsum[i] = 0.f;
    if (i < g)      g_gcnt[i] = 0.f;
}

// ---------------- degree histogram ----------------
__global__ void k_hist(const void* __restrict__ ei, int E)
{
    int e = blockIdx.x * blockDim.x + threadIdx.x;
    if (e >= E) return;
    int d;
    if (g_flags[0]) d = (int)((const long long*)ei)[(long long)E + e];
    else            d = ((const int*)ei)[E + e];
    atomicAdd(&g_deg[d], 1);
}

// ---------------- exclusive scan ----------------
__global__ void k_scan1(int n)
{
    __shared__ int sh[1024];
    int i = blockIdx.x * 1024 + threadIdx.x;
    int v = (i < n) ? g_deg[i] : 0;
    sh[threadIdx.x] = v;
    __syncthreads();
    for (int d = 1; d < 1024; d <<= 1) {
        int t = 0;
        if ((int)threadIdx.x >= d) t = sh[threadIdx.x - d];
        __syncthreads();
        sh[threadIdx.x] += t;
        __syncthreads();
    }
    if (i < n) g_off[i] = sh[threadIdx.x] - v;
    if (threadIdx.x == 1023) g_part[blockIdx.x] = sh[1023];
}

__global__ void k_scan2(int nblocks, int n)
{
    __shared__ int sh[256];
    if (threadIdx.x < nblocks) sh[threadIdx.x] = g_part[threadIdx.x];
    __syncthreads();
    if (threadIdx.x == 0) {
        int run = 0;
        for (int b = 0; b < nblocks; b++) { int t = sh[b]; sh[b] = run; run += t; }
        g_off[n] = run;
    }
    __syncthreads();
    if (threadIdx.x < nblocks) g_part[threadIdx.x] = sh[threadIdx.x];
}

__global__ void k_scan3(int n)
{
    int i = blockIdx.x * 1024 + threadIdx.x;
    if (i < n) g_off[i] += g_part[blockIdx.x];
}

// ---------------- scatter edges into CSR ----------------
__global__ void k_scatter(const void* __restrict__ ei, int E)
{
    int e = blockIdx.x * blockDim.x + threadIdx.x;
    if (e >= E) return;
    int s, d;
    if (g_flags[0]) {
        const long long* p = (const long long*)ei;
        s = (int)p[e]; d = (int)p[(long long)E + e];
    } else {
        const int* p = (const int*)ei;
        s = p[e]; d = p[E + e];
    }
    int pos = g_off[d] + atomicAdd(&g_cur[d], 1);
    g_csr[pos] = s;
}

// ---------------- GEMM + attention-logit precompute ----------------
template<int DIN>
__global__ void k_gemm(const float* __restrict__ xp, const float* __restrict__ W,
                       const float* __restrict__ asv, const float* __restrict__ adv, int n)
{
    __shared__ float Ws[DIN * 32];
    __shared__ float Ss[32], Sd[32];
    for (int i = threadIdx.x; i < DIN * 32; i += blockDim.x) Ws[i] = W[i];
    if (threadIdx.x < 32) { Ss[threadIdx.x] = asv[threadIdx.x]; Sd[threadIdx.x] = adv[threadIdx.x]; }
    __syncthreads();

    int node = blockIdx.x * blockDim.x + threadIdx.x;
    if (node >= n) return;

    const float* xin = xp ? xp : g_x;
    float acc[32];
#pragma unroll
    for (int j = 0; j < 32; j++) acc[j] = 0.f;

    const float4* xr = (const float4*)(xin + (size_t)node * DIN);
#pragma unroll 4
    for (int k4 = 0; k4 < DIN / 4; k4++) {
        float4 xv = __ldg(&xr[k4]);
        float xk[4] = { xv.x, xv.y, xv.z, xv.w };
#pragma unroll
        for (int kk = 0; kk < 4; kk++) {
            const float4* wr = (const float4*)&Ws[(k4 * 4 + kk) * 32];
#pragma unroll
            for (int j4 = 0; j4 < 8; j4++) {
                float4 w = wr[j4];
                acc[j4 * 4 + 0] += xk[kk] * w.x;
                acc[j4 * 4 + 1] += xk[kk] * w.y;
                acc[j4 * 4 + 2] += xk[kk] * w.z;
                acc[j4 * 4 + 3] += xk[kk] * w.w;
            }
        }
    }

    float alS[4], alD[4];
#pragma unroll
    for (int hh = 0; hh < 4; hh++) {
        float a = 0.f, b = 0.f;
#pragma unroll
        for (int c = 0; c < 8; c++) {
            a += acc[hh * 8 + c] * Ss[hh * 8 + c];
            b += acc[hh * 8 + c] * Sd[hh * 8 + c];
        }
        alS[hh] = a; alD[hh] = b;
    }

    // store h as fp16 (16 half2 = 64B)
    union { __half2 h2[8]; uint4 u[2]; } pk;
    uint4* hout = (uint4*)(g_h16 + (size_t)node * 16);
#pragma unroll
    for (int half_ = 0; half_ < 2; half_++) {
#pragma unroll
        for (int j = 0; j < 8; j++)
            pk.h2[j] = __floats2half2_rn(acc[half_ * 16 + 2 * j], acc[half_ * 16 + 2 * j + 1]);
        hout[half_ * 2 + 0] = pk.u[0];
        hout[half_ * 2 + 1] = pk.u[1];
    }
    *(float4*)(g_als + (size_t)node * 4) = make_float4(alS[0], alS[1], alS[2], alS[3]);
    *(float4*)(g_ald + (size_t)node * 4) = make_float4(alD[0], alD[1], alD[2], alD[3]);
}

// ---------------- aggregation: 4 lanes per node, fixed-shift softmax, fp16 gather ----------------
__global__ void __launch_bounds__(256, 2) k_agg(const float* __restrict__ bias, int n)
{
    int idx = blockIdx.x * blockDim.x + threadIdx.x;
    int node = idx >> 2;
    int hh   = idx & 3;
    if (node >= n) return;

    int off = g_off[node];
    int end = g_off[node + 1];
    float ad = __ldg(&g_ald[(size_t)node * 4 + hh]);

    // self-loop: shift = es, weight 1
    float es = __ldg(&g_als[(size_t)node * 4 + hh]) + ad;
    es = fmaxf(es, 0.2f * es);

    float s = 1.f;
    float a0, a1, a2, a3, a4, a5, a6, a7;
    {
        uint4 raw = __ldg((const uint4*)(g_h16 + (size_t)node * 16 + hh * 4));
        const __half2* p = (const __half2*)&raw;
        float2 f0 = __half22float2(p[0]);
        float2 f1 = __half22float2(p[1]);
        float2 f2 = __half22float2(p[2]);
        float2 f3 = __half22float2(p[3]);
        a0 = f0.x; a1 = f0.y; a2 = f1.x; a3 = f1.y;
        a4 = f2.x; a5 = f2.y; a6 = f3.x; a7 = f3.y;
    }

#pragma unroll 8
    for (int i = off; i < end; i++) {
        int sidx = __ldg(&g_csr[i]);
        float e = __ldg(&g_als[(size_t)sidx * 4 + hh]) + ad;
        e = fmaxf(e, 0.2f * e);                 // leaky_relu(0.2)
        float w = __expf(e - es);
        uint4 raw = __ldg((const uint4*)(g_h16 + (size_t)sidx * 16 + hh * 4));
        const __half2* p = (const __half2*)&raw;
        float2 f0 = __half22float2(p[0]);
        float2 f1 = __half22float2(p[1]);
        float2 f2 = __half22float2(p[2]);
        float2 f3 = __half22float2(p[3]);
        s  += w;
        a0 += w * f0.x;  a1 += w * f0.y;  a2 += w * f1.x;  a3 += w * f1.y;
        a4 += w * f2.x;  a5 += w * f2.y;  a6 += w * f3.x;  a7 += w * f3.y;
    }

    float inv = 1.f / s;
    const float* bp = bias + hh * 8;
    float v[8] = { a0*inv, a1*inv, a2*inv, a3*inv, a4*inv, a5*inv, a6*inv, a7*inv };
#pragma unroll
    for (int c = 0; c < 8; c++) {
        float t = v[c] + bp[c];
        v[c] = t > 0.f ? t : expm1f(t);         // elu
    }
    float4* xo = (float4*)(g_x + (size_t)node * HC + hh * 8);
    xo[0] = make_float4(v[0], v[1], v[2], v[3]);
    xo[1] = make_float4(v[4], v[5], v[6], v[7]);
}

// ---------------- global mean pool: warp-segmented ----------------
__global__ void k_pool(const void* __restrict__ batch, int n)
{
    int warp = (blockIdx.x * blockDim.x + threadIdx.x) >> 5;
    int lane = threadIdx.x & 31;
    int base = warp * 32;
    if (base >= n) return;
    int is64 = g_flags[1];

    float accv = 0.f; int cnt = 0; int curg = -1;
    for (int j = 0; j < 32; j++) {
        int node = base + j;
        if (node >= n) break;
        int gg;
        if (is64) gg = (int)((const long long*)batch)[node];
        else      gg = ((const int*)batch)[node];
        if (gg != curg) {
            if (curg >= 0) {
                atomicAdd(&g_gsum[curg * HC + lane], accv);
                if (lane == 0) atomicAdd(&g_gcnt[curg], (float)cnt);
            }
            accv = 0.f; cnt = 0; curg = gg;
        }
        accv += g_x[(size_t)node * HC + lane];
        cnt++;
    }
    if (curg >= 0) {
        atomicAdd(&g_gsum[curg * HC + lane], accv);
        if (lane == 0) atomicAdd(&g_gcnt[curg], (float)cnt);
    }
}

// ---------------- final FC ----------------
__global__ void k_final(const float* __restrict__ fcw, const float* __restrict__ fcb,
                        float* __restrict__ out, int gcount)
{
    int g = blockIdx.x * blockDim.x + threadIdx.x;
    if (g >= gcount) return;
    float cnt = fmaxf(g_gcnt[g], 1.f);
    float acc = fcb[0];
    const float* s = g_gsum + g * HC;
#pragma unroll
    for (int c = 0; c < HC; c++) acc += (s[c] / cnt) * fcw[c];
    out[g] = acc;
}

// ---------------- host ----------------
extern "C" void kernel_launch(void* const* d_in, const int* in_sizes, int n_in,
                              void* d_out, int out_size)
{
    const float* x     = (const float*)d_in[0];
    const void*  ei    = d_in[1];
    const void*  batch = d_in[2];
    const float* W1 = (const float*)d_in[3];
    const float* as1= (const float*)d_in[4];
    const float* ad1= (const float*)d_in[5];
    const float* b1 = (const float*)d_in[6];
    const float* W2 = (const float*)d_in[7];
    const float* as2= (const float*)d_in[8];
    const float* ad2= (const float*)d_in[9];
    const float* b2 = (const float*)d_in[10];
    const float* W3 = (const float*)d_in[11];
    const float* as3= (const float*)d_in[12];
    const float* ad3= (const float*)d_in[13];
    const float* b3 = (const float*)d_in[14];
    const float* W4 = (const float*)d_in[15];
    const float* as4= (const float*)d_in[16];
    const float* ad4= (const float*)d_in[17];
    const float* b4 = (const float*)d_in[18];
    const float* fcw= (const float*)d_in[19];
    const float* fcb= (const float*)d_in[20];

    int nN = in_sizes[2];
    int E  = in_sizes[1] / 2;
    int G  = out_size;
    float* out = (float*)d_out;

    k_detect<<<1, 32>>>((const int*)ei, in_sizes[1], (const int*)batch, nN);

    {
        int mx = nN;
        if (G * HC > mx) mx = G * HC;
        k_init<<<(mx + 255) / 256, 256>>>(nN, G);
    }

    k_hist<<<(E + 255) / 256, 256>>>(ei, E);

    int nb = (nN + 1023) / 1024;
    k_scan1<<<nb, 1024>>>(nN);
    k_scan2<<<1, 256>>>(nb, nN);
    k_scan3<<<nb, 1024>>>(nN);

    k_scatter<<<(E + 255) / 256, 256>>>(ei, E);

    int gb = (nN + 255) / 256;
    int ab = (nN * 4 + 255) / 256;    // 4 lanes per node

    k_gemm<128><<<gb, 256>>>(x,      W1, as1, ad1, nN);
    k_agg<<<ab, 256>>>(b1, nN);
    k_gemm<32><<<gb, 256>>>(nullptr, W2, as2, ad2, nN);
    k_agg<<<ab, 256>>>(b2, nN);
    k_gemm<32><<<gb, 256>>>(nullptr, W3, as3, ad3, nN);
    k_agg<<<ab, 256>>>(b3, nN);
    k_gemm<32><<<gb, 256>>>(nullptr, W4, as4, ad4, nN);
    k_agg<<<ab, 256>>>(b4, nN);

    k_pool<<<(nN + 255) / 256, 256>>>(batch, nN);
    k_final<<<(G + 255) / 256, 256>>>(fcw, fcb, out, G);
}